// round 2
// baseline (speedup 1.0000x reference)
#include <cuda_runtime.h>

#define NN 100000
#define NE 3200000
#define NG 64
#define HID 64
#define EPS 1e-5f

// Scratch (allocation-free rule: __device__ globals)
__device__ float4 d_xn[NN];     // batch-normalized x
__device__ float4 d_a1[NN];     // agg_x then a1
__device__ float  d_deg[NN];
__device__ float  d_dinv[NN];
__device__ double d_sum[4];
__device__ double d_sumsq[4];
// per graph: [0..3]=E4, [4]=Es, [5..8]=N4, [9]=Ns, [10]=nG, [11]=pad
__device__ float  d_acc[NG * 12];

__global__ void k_init() {
    int i = blockIdx.x * blockDim.x + threadIdx.x;
    int stride = gridDim.x * blockDim.x;
    float* a1f = (float*)d_a1;
    for (int j = i; j < NN * 4; j += stride) a1f[j] = 0.f;
    for (int j = i; j < NN; j += stride) d_deg[j] = 1.f;   // self-loop
    for (int j = i; j < NG * 12; j += stride) d_acc[j] = 0.f;
    if (i < 4) { d_sum[i] = 0.0; d_sumsq[i] = 0.0; }
}

__global__ void k_stats(const float* __restrict__ x) {
    double s0 = 0, s1 = 0, s2 = 0, s3 = 0;
    double q0 = 0, q1 = 0, q2 = 0, q3 = 0;
    int stride = gridDim.x * blockDim.x;
    for (int j = blockIdx.x * blockDim.x + threadIdx.x; j < NN; j += stride) {
        float4 v = ((const float4*)x)[j];
        s0 += v.x; q0 += (double)v.x * v.x;
        s1 += v.y; q1 += (double)v.y * v.y;
        s2 += v.z; q2 += (double)v.z * v.z;
        s3 += v.w; q3 += (double)v.w * v.w;
    }
    #pragma unroll
    for (int o = 16; o > 0; o >>= 1) {
        s0 += __shfl_down_sync(0xffffffffu, s0, o);
        s1 += __shfl_down_sync(0xffffffffu, s1, o);
        s2 += __shfl_down_sync(0xffffffffu, s2, o);
        s3 += __shfl_down_sync(0xffffffffu, s3, o);
        q0 += __shfl_down_sync(0xffffffffu, q0, o);
        q1 += __shfl_down_sync(0xffffffffu, q1, o);
        q2 += __shfl_down_sync(0xffffffffu, q2, o);
        q3 += __shfl_down_sync(0xffffffffu, q3, o);
    }
    if ((threadIdx.x & 31) == 0) {
        atomicAdd(&d_sum[0], s0); atomicAdd(&d_sumsq[0], q0);
        atomicAdd(&d_sum[1], s1); atomicAdd(&d_sumsq[1], q1);
        atomicAdd(&d_sum[2], s2); atomicAdd(&d_sumsq[2], q2);
        atomicAdd(&d_sum[3], s3); atomicAdd(&d_sumsq[3], q3);
    }
}

__global__ void k_deg(const int* __restrict__ ei) {
    int e = blockIdx.x * blockDim.x + threadIdx.x;
    if (e < NE) atomicAdd(&d_deg[ei[NE + e]], 1.0f);
}

__global__ void k_node1(const float* __restrict__ x,
                        const float* __restrict__ g0,
                        const float* __restrict__ b0) {
    int i = blockIdx.x * blockDim.x + threadIdx.x;
    if (i >= NN) return;
    float mu[4], sc[4], sh[4];
    #pragma unroll
    for (int c = 0; c < 4; c++) {
        double m = d_sum[c] / (double)NN;
        double var = d_sumsq[c] / (double)NN - m * m;
        mu[c] = (float)m;
        sc[c] = rsqrtf((float)var + EPS) * g0[c];
        sh[c] = b0[c];
    }
    float4 v = ((const float4*)x)[i];
    float4 o;
    o.x = (v.x - mu[0]) * sc[0] + sh[0];
    o.y = (v.y - mu[1]) * sc[1] + sh[1];
    o.z = (v.z - mu[2]) * sc[2] + sh[2];
    o.w = (v.w - mu[3]) * sc[3] + sh[3];
    d_xn[i] = o;
    d_dinv[i] = rsqrtf(d_deg[i]);
}

__global__ void k_edge1(const int* __restrict__ ei) {
    int e = blockIdx.x * blockDim.x + threadIdx.x;
    if (e >= NE) return;
    int s = ei[e];
    int d = ei[NE + e];
    float w = d_dinv[s] * d_dinv[d];
    float4 v = d_xn[s];
    float* p = (float*)&d_a1[d];
    atomicAdd(p + 0, w * v.x);
    atomicAdd(p + 1, w * v.y);
    atomicAdd(p + 2, w * v.z);
    atomicAdd(p + 3, w * v.w);
}

__global__ void k_node2(const int* __restrict__ batch) {
    __shared__ float sacc[NG * 6];
    for (int j = threadIdx.x; j < NG * 6; j += blockDim.x) sacc[j] = 0.f;
    __syncthreads();
    int stride = gridDim.x * blockDim.x;
    for (int i = blockIdx.x * blockDim.x + threadIdx.x; i < NN; i += stride) {
        float di = d_dinv[i];
        float inv = di * di;   // 1/deg
        float4 a = d_a1[i];
        float4 xv = d_xn[i];
        a.x += xv.x * inv; a.y += xv.y * inv;
        a.z += xv.z * inv; a.w += xv.w * inv;
        d_a1[i] = a;           // a1 = agg_x + xn/deg
        int g = batch[i];
        float* p = &sacc[g * 6];
        atomicAdd(p + 0, a.x * inv);
        atomicAdd(p + 1, a.y * inv);
        atomicAdd(p + 2, a.z * inv);
        atomicAdd(p + 3, a.w * inv);
        atomicAdd(p + 4, inv);
        atomicAdd(p + 5, 1.0f);
    }
    __syncthreads();
    for (int j = threadIdx.x; j < NG * 6; j += blockDim.x) {
        int g = j / 6, c = j % 6;
        atomicAdd(&d_acc[g * 12 + 5 + c], sacc[j]);
    }
}

__global__ void k_edge2(const int* __restrict__ ei,
                        const int* __restrict__ batch) {
    __shared__ float sacc[NG * 5];
    for (int j = threadIdx.x; j < NG * 5; j += blockDim.x) sacc[j] = 0.f;
    __syncthreads();
    int stride = gridDim.x * blockDim.x;
    for (int e = blockIdx.x * blockDim.x + threadIdx.x; e < NE; e += stride) {
        int s = ei[e];
        int d = ei[NE + e];
        float w = d_dinv[s] * d_dinv[d];
        int g = batch[d];
        float4 a = d_a1[s];
        float* p = &sacc[g * 5];
        atomicAdd(p + 0, w * a.x);
        atomicAdd(p + 1, w * a.y);
        atomicAdd(p + 2, w * a.z);
        atomicAdd(p + 3, w * a.w);
        atomicAdd(p + 4, w);
    }
    __syncthreads();
    for (int j = threadIdx.x; j < NG * 5; j += blockDim.x) {
        int g = j / 5, c = j % 5;
        atomicAdd(&d_acc[g * 12 + c], sacc[j]);
    }
}

// One block, 64 threads: per-graph assembly, W0/W1 apply, BN over graphs, MLP
__global__ void k_final(const float* __restrict__ W0, const float* __restrict__ b0,
                        const float* __restrict__ W1, const float* __restrict__ b1,
                        const float* __restrict__ bn1g, const float* __restrict__ bn1b,
                        const float* __restrict__ l0W, const float* __restrict__ l0b,
                        const float* __restrict__ l1W, const float* __restrict__ l1b,
                        const float* __restrict__ oW, const float* __restrict__ ob,
                        float* __restrict__ out) {
    __shared__ float sg[64][65];
    __shared__ float sW[64 * 64];
    int t = threadIdx.x;  // graph id / feature id

    // load W1 to shared
    for (int j = t; j < 4096; j += 64) sW[j] = W1[j];

    const float* acc = &d_acc[t * 12];
    float s4[4];
    #pragma unroll
    for (int c = 0; c < 4; c++) s4[c] = acc[c] + acc[5 + c];
    float ss = acc[4] + acc[9];
    float ng = acc[10];

    float h[64];
    #pragma unroll
    for (int j = 0; j < 64; j++)
        h[j] = ss * b0[j] + s4[0] * W0[j] + s4[1] * W0[64 + j]
             + s4[2] * W0[128 + j] + s4[3] * W0[192 + j];
    __syncthreads();

    // g = h @ W1 + ng*b1
    for (int j = 0; j < 64; j++) {
        float a = ng * b1[j];
        #pragma unroll
        for (int k = 0; k < 64; k++) a += h[k] * sW[k * 64 + j];
        sg[t][j] = a;
    }
    __syncthreads();

    // BN1 over graphs, feature f = t
    {
        float m = 0.f;
        for (int G = 0; G < 64; G++) m += sg[G][t];
        m *= (1.0f / 64.0f);
        float v = 0.f;
        for (int G = 0; G < 64; G++) { float d = sg[G][t] - m; v += d * d; }
        v *= (1.0f / 64.0f);
        float r = rsqrtf(v + EPS) * bn1g[t];
        float bb = bn1b[t];
        for (int G = 0; G < 64; G++) sg[G][t] = (sg[G][t] - m) * r + bb;
    }
    __syncthreads();

    // lin0
    float h2[64];
    #pragma unroll
    for (int k = 0; k < 64; k++) h2[k] = sg[t][k];
    __syncthreads();
    for (int j = t; j < 4096; j += 64) sW[j] = l0W[j];
    __syncthreads();
    for (int j = 0; j < 64; j++) {
        float a = l0b[j];
        #pragma unroll
        for (int k = 0; k < 64; k++) a += h2[k] * sW[k * 64 + j];
        sg[t][j] = a;
    }
    __syncthreads();

    // lin1 + out fused
    #pragma unroll
    for (int k = 0; k < 64; k++) h2[k] = sg[t][k];
    __syncthreads();
    for (int j = t; j < 4096; j += 64) sW[j] = l1W[j];
    __syncthreads();
    float o = ob[0];
    for (int j = 0; j < 64; j++) {
        float a = l1b[j];
        #pragma unroll
        for (int k = 0; k < 64; k++) a += h2[k] * sW[k * 64 + j];
        o += a * oW[j];
    }
    out[t] = o;
}

extern "C" void kernel_launch(void* const* d_in, const int* in_sizes, int n_in,
                              void* d_out, int out_size) {
    const float* x     = (const float*)d_in[0];
    const int*   ei    = (const int*)d_in[1];
    const int*   batch = (const int*)d_in[2];
    const float* bn0g = (const float*)d_in[3];
    const float* bn0b = (const float*)d_in[4];
    const float* W0   = (const float*)d_in[5];
    const float* b0   = (const float*)d_in[6];
    const float* W1   = (const float*)d_in[7];
    const float* b1   = (const float*)d_in[8];
    const float* bn1g = (const float*)d_in[9];
    const float* bn1b = (const float*)d_in[10];
    const float* l0W  = (const float*)d_in[11];
    const float* l0b  = (const float*)d_in[12];
    const float* l1W  = (const float*)d_in[13];
    const float* l1b  = (const float*)d_in[14];
    const float* oW   = (const float*)d_in[15];
    const float* ob   = (const float*)d_in[16];
    float* out = (float*)d_out;

    k_init<<<512, 256>>>();
    k_stats<<<256, 256>>>(x);
    k_deg<<<(NE + 255) / 256, 256>>>(ei);
    k_node1<<<(NN + 255) / 256, 256>>>(x, bn0g, bn0b);
    k_edge1<<<(NE + 255) / 256, 256>>>(ei);
    k_node2<<<296, 256>>>(batch);
    k_edge2<<<592, 256>>>(ei, batch);
    k_final<<<1, 64>>>(W0, b0, W1, b1, bn1g, bn1b,
                       l0W, l0b, l1W, l1b, oW, ob, out);
}

// round 4
// speedup vs baseline: 1.3251x; 1.3251x over previous
#include <cuda_runtime.h>

#define NN 100000
#define NE 3200000
#define NG 64
#define EPS 1e-5f

// Scratch (__device__ globals per allocation-free rule)
__device__ float4 d_xn[NN];     // batch-normalized x
__device__ float4 d_y[NN];      // dinv * xn
__device__ float4 d_a1[NN];     // agg accumulator, then z = dinv*a1
__device__ float4 d_m[NN];      // layer2 per-node v4 accumulator
__device__ float  d_n[NN];      // layer2 per-node scalar accumulator
__device__ float  d_deg[NN];
__device__ float  d_dinv[NN];
__device__ double d_sum[4];
__device__ double d_sumsq[4];
__device__ float  d_bn[8];      // mu[4], scale[4]
// per graph: [0..3]=s4, [4]=ss, [5]=ng
__device__ float  d_acc[NG * 8];

__device__ __forceinline__ void red4(float4* p, float a, float b, float c, float d) {
    asm volatile("red.global.add.v4.f32 [%0], {%1,%2,%3,%4};"
                 :: "l"(p), "f"(a), "f"(b), "f"(c), "f"(d) : "memory");
}
__device__ __forceinline__ void red1(float* p, float a) {
    asm volatile("red.global.add.f32 [%0], %1;" :: "l"(p), "f"(a) : "memory");
}

__global__ void k_init() {
    int i = blockIdx.x * blockDim.x + threadIdx.x;
    int stride = gridDim.x * blockDim.x;
    float* a1f = (float*)d_a1;
    float* mf = (float*)d_m;
    for (int j = i; j < NN * 4; j += stride) { a1f[j] = 0.f; mf[j] = 0.f; }
    for (int j = i; j < NN; j += stride) { d_deg[j] = 1.f; d_n[j] = 0.f; }
    for (int j = i; j < NG * 8; j += stride) d_acc[j] = 0.f;
    if (i < 4) { d_sum[i] = 0.0; d_sumsq[i] = 0.0; }
}

__global__ void k_stats(const float* __restrict__ x) {
    double s0 = 0, s1 = 0, s2 = 0, s3 = 0;
    double q0 = 0, q1 = 0, q2 = 0, q3 = 0;
    int stride = gridDim.x * blockDim.x;
    for (int j = blockIdx.x * blockDim.x + threadIdx.x; j < NN; j += stride) {
        float4 v = ((const float4*)x)[j];
        s0 += v.x; q0 += (double)v.x * v.x;
        s1 += v.y; q1 += (double)v.y * v.y;
        s2 += v.z; q2 += (double)v.z * v.z;
        s3 += v.w; q3 += (double)v.w * v.w;
    }
    #pragma unroll
    for (int o = 16; o > 0; o >>= 1) {
        s0 += __shfl_down_sync(0xffffffffu, s0, o);
        s1 += __shfl_down_sync(0xffffffffu, s1, o);
        s2 += __shfl_down_sync(0xffffffffu, s2, o);
        s3 += __shfl_down_sync(0xffffffffu, s3, o);
        q0 += __shfl_down_sync(0xffffffffu, q0, o);
        q1 += __shfl_down_sync(0xffffffffu, q1, o);
        q2 += __shfl_down_sync(0xffffffffu, q2, o);
        q3 += __shfl_down_sync(0xffffffffu, q3, o);
    }
    if ((threadIdx.x & 31) == 0) {
        atomicAdd(&d_sum[0], s0); atomicAdd(&d_sumsq[0], q0);
        atomicAdd(&d_sum[1], s1); atomicAdd(&d_sumsq[1], q1);
        atomicAdd(&d_sum[2], s2); atomicAdd(&d_sumsq[2], q2);
        atomicAdd(&d_sum[3], s3); atomicAdd(&d_sumsq[3], q3);
    }
}

__global__ void k_deg(const int* __restrict__ ei) {
    int e = blockIdx.x * blockDim.x + threadIdx.x;
    if (e < NE) red1(&d_deg[ei[NE + e]], 1.0f);
}

// one warp: compute BN0 mu/scale in fp64 exactly once
__global__ void k_prep(const float* __restrict__ g0) {
    int c = threadIdx.x;
    if (c < 4) {
        double m = d_sum[c] / (double)NN;
        double var = d_sumsq[c] / (double)NN - m * m;
        d_bn[c] = (float)m;
        d_bn[4 + c] = rsqrtf((float)var + EPS) * g0[c];
    }
}

__global__ void k_node1(const float* __restrict__ x,
                        const float* __restrict__ b0) {
    int i = blockIdx.x * blockDim.x + threadIdx.x;
    if (i >= NN) return;
    float4 v = ((const float4*)x)[i];
    float4 o;
    o.x = (v.x - d_bn[0]) * d_bn[4] + b0[0];
    o.y = (v.y - d_bn[1]) * d_bn[5] + b0[1];
    o.z = (v.z - d_bn[2]) * d_bn[6] + b0[2];
    o.w = (v.w - d_bn[3]) * d_bn[7] + b0[3];
    d_xn[i] = o;
    float di = rsqrtf(d_deg[i]);
    d_dinv[i] = di;
    float4 y;
    y.x = o.x * di; y.y = o.y * di; y.z = o.z * di; y.w = o.w * di;
    d_y[i] = y;
}

__global__ void k_edge1(const int* __restrict__ ei) {
    int e = blockIdx.x * blockDim.x + threadIdx.x;
    if (e >= NE) return;
    int s = ei[e];
    int d = ei[NE + e];
    float dd = d_dinv[d];
    float4 y = d_y[s];
    red4(&d_a1[d], dd * y.x, dd * y.y, dd * y.z, dd * y.w);
}

// z = dinv * (agg + xn/deg), stored back into d_a1
__global__ void k_node2() {
    int i = blockIdx.x * blockDim.x + threadIdx.x;
    if (i >= NN) return;
    float di = d_dinv[i];
    float inv = di * di;
    float4 a = d_a1[i];
    float4 xv = d_xn[i];
    float4 z;
    z.x = (a.x + xv.x * inv) * di;
    z.y = (a.y + xv.y * inv) * di;
    z.z = (a.z + xv.z * inv) * di;
    z.w = (a.w + xv.w * inv) * di;
    d_a1[i] = z;
}

__global__ void k_edge2(const int* __restrict__ ei) {
    int e = blockIdx.x * blockDim.x + threadIdx.x;
    if (e >= NE) return;
    int s = ei[e];
    int d = ei[NE + e];
    float4 z = d_a1[s];
    red4(&d_m[d], z.x, z.y, z.z, z.w);
    red1(&d_n[d], d_dinv[s]);
}

// per-graph reduction per node i:
//   E4_i = di*m[i]            (edge contributions into i)
//   N4_i = a1[i]/deg = z[i]*di  (self-loop)
//   => s4 contribution = di*(m[i] + z[i])
//   ss contribution = di*(n[i] + di);  ng contribution = 1
#define NCOPY 4
__global__ void k_node3(const int* __restrict__ batch) {
    __shared__ float sacc[NCOPY][NG * 6];
    for (int j = threadIdx.x; j < NCOPY * NG * 6; j += blockDim.x)
        ((float*)sacc)[j] = 0.f;
    __syncthreads();
    int w = (threadIdx.x >> 5) & (NCOPY - 1);
    int stride = gridDim.x * blockDim.x;
    for (int i = blockIdx.x * blockDim.x + threadIdx.x; i < NN; i += stride) {
        float di = d_dinv[i];
        float4 m = d_m[i];
        float4 z = d_a1[i];
        float n = d_n[i];
        int g = batch[i];
        float* p = &sacc[w][g * 6];
        atomicAdd(p + 0, di * (m.x + z.x));
        atomicAdd(p + 1, di * (m.y + z.y));
        atomicAdd(p + 2, di * (m.z + z.z));
        atomicAdd(p + 3, di * (m.w + z.w));
        atomicAdd(p + 4, di * (n + di));
        atomicAdd(p + 5, 1.0f);
    }
    __syncthreads();
    for (int j = threadIdx.x; j < NG * 6; j += blockDim.x) {
        float v = 0.f;
        #pragma unroll
        for (int k = 0; k < NCOPY; k++) v += sacc[k][j];
        int g = j / 6, c = j % 6;
        red1(&d_acc[g * 8 + c], v);
    }
}

// One block, 64 threads: W0/W1 apply, BN over graphs, MLP
__global__ void k_final(const float* __restrict__ W0, const float* __restrict__ b0,
                        const float* __restrict__ W1, const float* __restrict__ b1,
                        const float* __restrict__ bn1g, const float* __restrict__ bn1b,
                        const float* __restrict__ l0W, const float* __restrict__ l0b,
                        const float* __restrict__ l1W, const float* __restrict__ l1b,
                        const float* __restrict__ oW, const float* __restrict__ ob,
                        float* __restrict__ out) {
    __shared__ float sg[64][65];
    __shared__ float sW[64 * 64];
    int t = threadIdx.x;  // graph id / feature id

    for (int j = t; j < 4096; j += 64) sW[j] = W1[j];

    const float* acc = &d_acc[t * 8];
    float s4[4];
    #pragma unroll
    for (int c = 0; c < 4; c++) s4[c] = acc[c];
    float ss = acc[4];
    float ng = acc[5];

    // h = s4 @ W0 + ss * b0
    float h[64];
    #pragma unroll
    for (int j = 0; j < 64; j++)
        h[j] = ss * b0[j] + s4[0] * W0[j] + s4[1] * W0[64 + j]
             + s4[2] * W0[128 + j] + s4[3] * W0[192 + j];
    __syncthreads();

    // g = h @ W1 + ng*b1
    for (int j = 0; j < 64; j++) {
        float a = ng * b1[j];
        #pragma unroll
        for (int k = 0; k < 64; k++) a += h[k] * sW[k * 64 + j];
        sg[t][j] = a;
    }
    __syncthreads();

    // BN1 over graphs, feature f = t
    {
        float m = 0.f;
        for (int G = 0; G < 64; G++) m += sg[G][t];
        m *= (1.0f / 64.0f);
        float v = 0.f;
        for (int G = 0; G < 64; G++) { float d = sg[G][t] - m; v += d * d; }
        v *= (1.0f / 64.0f);
        float r = rsqrtf(v + EPS) * bn1g[t];
        float bb = bn1b[t];
        for (int G = 0; G < 64; G++) sg[G][t] = (sg[G][t] - m) * r + bb;
    }
    __syncthreads();

    // lin0
    float h2[64];
    #pragma unroll
    for (int k = 0; k < 64; k++) h2[k] = sg[t][k];
    __syncthreads();
    for (int j = t; j < 4096; j += 64) sW[j] = l0W[j];
    __syncthreads();
    for (int j = 0; j < 64; j++) {
        float a = l0b[j];
        #pragma unroll
        for (int k = 0; k < 64; k++) a += h2[k] * sW[k * 64 + j];
        sg[t][j] = a;
    }
    __syncthreads();

    // lin1 + out fused
    #pragma unroll
    for (int k = 0; k < 64; k++) h2[k] = sg[t][k];
    __syncthreads();
    for (int j = t; j < 4096; j += 64) sW[j] = l1W[j];
    __syncthreads();
    float o = ob[0];
    for (int j = 0; j < 64; j++) {
        float a = l1b[j];
        #pragma unroll
        for (int k = 0; k < 64; k++) a += h2[k] * sW[k * 64 + j];
        o += a * oW[j];
    }
    out[t] = o;
}

extern "C" void kernel_launch(void* const* d_in, const int* in_sizes, int n_in,
                              void* d_out, int out_size) {
    const float* x     = (const float*)d_in[0];
    const int*   ei    = (const int*)d_in[1];
    const int*   batch = (const int*)d_in[2];
    const float* bn0g = (const float*)d_in[3];
    const float* bn0b = (const float*)d_in[4];
    const float* W0   = (const float*)d_in[5];
    const float* b0   = (const float*)d_in[6];
    const float* W1   = (const float*)d_in[7];
    const float* b1   = (const float*)d_in[8];
    const float* bn1g = (const float*)d_in[9];
    const float* bn1b = (const float*)d_in[10];
    const float* l0W  = (const float*)d_in[11];
    const float* l0b  = (const float*)d_in[12];
    const float* l1W  = (const float*)d_in[13];
    const float* l1b  = (const float*)d_in[14];
    const float* oW   = (const float*)d_in[15];
    const float* ob   = (const float*)d_in[16];
    float* out = (float*)d_out;

    k_init<<<512, 256>>>();
    k_stats<<<256, 256>>>(x);
    k_deg<<<(NE + 255) / 256, 256>>>(ei);
    k_prep<<<1, 32>>>(bn0g);
    k_node1<<<(NN + 255) / 256, 256>>>(x, bn0b);
    k_edge1<<<(NE + 255) / 256, 256>>>(ei);
    k_node2<<<(NN + 255) / 256, 256>>>();
    k_edge2<<<(NE + 255) / 256, 256>>>(ei);
    k_node3<<<148, 256>>>(batch);
    k_final<<<1, 64>>>(W0, b0, W1, b1, bn1g, bn1b,
                       l0W, l0b, l1W, l1b, oW, ob, out);
}

// round 5
// speedup vs baseline: 1.4677x; 1.1076x over previous
#include <cuda_runtime.h>

#define NN 100000
#define NE 3200000
#define NG 64
#define EPS 1e-5f

// Scratch (__device__ globals; all accumulators are zero at rest — each kernel
// that last reads an accumulator resets it for the next graph replay).
__device__ float4 d_xn[NN];     // batch-normalized x           (overwritten each run)
__device__ float4 d_y[NN];      // dinv * xn                    (overwritten each run)
__device__ float4 d_a1[NN];     // raw agg, then z = dinv*a1    (accumulator, reset in node3)
__device__ float4 d_m[NN];      // layer2 v4 accumulator        (reset in node3)
__device__ float  d_n[NN];      // layer2 scalar accumulator    (reset in node3)
__device__ float  d_degx[NN];   // degree minus 1 (self-loop)   (reset in node3)
__device__ float  d_dinv[NN];   // overwritten each run
__device__ double d_sum[4];     // reset in node2
__device__ double d_sumsq[4];   // reset in node2
__device__ float  d_acc[NG * 8];// per graph: [0..3]=s4, [4]=ss, [5]=ng (reset in final)

__device__ __forceinline__ void red4(float4* p, float a, float b, float c, float d) {
    asm volatile("red.global.add.v4.f32 [%0], {%1,%2,%3,%4};"
                 :: "l"(p), "f"(a), "f"(b), "f"(c), "f"(d) : "memory");
}
__device__ __forceinline__ void red4v(float4* p, float4 v) {
    asm volatile("red.global.add.v4.f32 [%0], {%1,%2,%3,%4};"
                 :: "l"(p), "f"(v.x), "f"(v.y), "f"(v.z), "f"(v.w) : "memory");
}
__device__ __forceinline__ void red1(float* p, float a) {
    asm volatile("red.global.add.f32 [%0], %1;" :: "l"(p), "f"(a) : "memory");
}

// Fused: degree accumulation (4 edges/thread) + BN0 statistics
__global__ void k_pre(const float* __restrict__ x, const int* __restrict__ ei) {
    int t = blockIdx.x * blockDim.x + threadIdx.x;
    if (t < NE / 4) {
        int4 d = ((const int4*)(ei + NE))[t];
        red1(&d_degx[d.x], 1.0f);
        red1(&d_degx[d.y], 1.0f);
        red1(&d_degx[d.z], 1.0f);
        red1(&d_degx[d.w], 1.0f);
    }
    if (blockIdx.x < 256) {
        int j0 = blockIdx.x * blockDim.x + threadIdx.x;
        int stride = 256 * blockDim.x;
        double s0 = 0, s1 = 0, s2 = 0, s3 = 0;
        double q0 = 0, q1 = 0, q2 = 0, q3 = 0;
        for (int j = j0; j < NN; j += stride) {
            float4 v = ((const float4*)x)[j];
            s0 += v.x; q0 += (double)v.x * v.x;
            s1 += v.y; q1 += (double)v.y * v.y;
            s2 += v.z; q2 += (double)v.z * v.z;
            s3 += v.w; q3 += (double)v.w * v.w;
        }
        #pragma unroll
        for (int o = 16; o > 0; o >>= 1) {
            s0 += __shfl_down_sync(0xffffffffu, s0, o);
            s1 += __shfl_down_sync(0xffffffffu, s1, o);
            s2 += __shfl_down_sync(0xffffffffu, s2, o);
            s3 += __shfl_down_sync(0xffffffffu, s3, o);
            q0 += __shfl_down_sync(0xffffffffu, q0, o);
            q1 += __shfl_down_sync(0xffffffffu, q1, o);
            q2 += __shfl_down_sync(0xffffffffu, q2, o);
            q3 += __shfl_down_sync(0xffffffffu, q3, o);
        }
        if ((threadIdx.x & 31) == 0) {
            atomicAdd(&d_sum[0], s0); atomicAdd(&d_sumsq[0], q0);
            atomicAdd(&d_sum[1], s1); atomicAdd(&d_sumsq[1], q1);
            atomicAdd(&d_sum[2], s2); atomicAdd(&d_sumsq[2], q2);
            atomicAdd(&d_sum[3], s3); atomicAdd(&d_sumsq[3], q3);
        }
    }
}

// BN0 normalize + dinv; BN constants computed per block (one thread, smem bcast)
__global__ void k_node1(const float* __restrict__ x,
                        const float* __restrict__ g0,
                        const float* __restrict__ b0) {
    __shared__ float sbn[12];  // mu[4], scale[4], shift[4]
    if (threadIdx.x == 0) {
        #pragma unroll
        for (int c = 0; c < 4; c++) {
            double m = d_sum[c] / (double)NN;
            double var = d_sumsq[c] / (double)NN - m * m;
            sbn[c] = (float)m;
            sbn[4 + c] = rsqrtf((float)var + EPS) * g0[c];
            sbn[8 + c] = b0[c];
        }
    }
    __syncthreads();
    int i = blockIdx.x * blockDim.x + threadIdx.x;
    if (i >= NN) return;
    float4 v = ((const float4*)x)[i];
    float4 o;
    o.x = (v.x - sbn[0]) * sbn[4] + sbn[8];
    o.y = (v.y - sbn[1]) * sbn[5] + sbn[9];
    o.z = (v.z - sbn[2]) * sbn[6] + sbn[10];
    o.w = (v.w - sbn[3]) * sbn[7] + sbn[11];
    d_xn[i] = o;
    float di = rsqrtf(d_degx[i] + 1.0f);
    d_dinv[i] = di;
    float4 y;
    y.x = o.x * di; y.y = o.y * di; y.z = o.z * di; y.w = o.w * di;
    d_y[i] = y;
}

// agg_raw[d] += y[s]   (dinv[d] folded into node2), 4 edges/thread
__global__ void k_edge1(const int* __restrict__ ei) {
    int t = blockIdx.x * blockDim.x + threadIdx.x;
    if (t >= NE / 4) return;
    int4 s = ((const int4*)ei)[t];
    int4 d = ((const int4*)(ei + NE))[t];
    red4v(&d_a1[d.x], d_y[s.x]);
    red4v(&d_a1[d.y], d_y[s.y]);
    red4v(&d_a1[d.z], d_y[s.z]);
    red4v(&d_a1[d.w], d_y[s.w]);
}

// z = dinv*a1 = di^2*agg_raw + di^3*xn ; also reset BN sums for next replay
__global__ void k_node2() {
    int i = blockIdx.x * blockDim.x + threadIdx.x;
    if (blockIdx.x == 0 && threadIdx.x < 4) {
        d_sum[threadIdx.x] = 0.0;
        d_sumsq[threadIdx.x] = 0.0;
    }
    if (i >= NN) return;
    float di = d_dinv[i];
    float di2 = di * di;
    float di3 = di2 * di;
    float4 a = d_a1[i];
    float4 xv = d_xn[i];
    float4 z;
    z.x = a.x * di2 + xv.x * di3;
    z.y = a.y * di2 + xv.y * di3;
    z.z = a.z * di2 + xv.z * di3;
    z.w = a.w * di2 + xv.w * di3;
    d_a1[i] = z;
}

// m[d] += z[s]; n[d] += dinv[s], 4 edges/thread
__global__ void k_edge2(const int* __restrict__ ei) {
    int t = blockIdx.x * blockDim.x + threadIdx.x;
    if (t >= NE / 4) return;
    int4 s = ((const int4*)ei)[t];
    int4 d = ((const int4*)(ei + NE))[t];
    red4v(&d_m[d.x], d_a1[s.x]); red1(&d_n[d.x], d_dinv[s.x]);
    red4v(&d_m[d.y], d_a1[s.y]); red1(&d_n[d.y], d_dinv[s.y]);
    red4v(&d_m[d.z], d_a1[s.z]); red1(&d_n[d.z], d_dinv[s.z]);
    red4v(&d_m[d.w], d_a1[s.w]); red1(&d_n[d.w], d_dinv[s.w]);
}

// per-graph reduction; also resets node accumulators for next replay
#define NCOPY 4
__global__ void k_node3(const int* __restrict__ batch) {
    __shared__ float sacc[NCOPY][NG * 6];
    for (int j = threadIdx.x; j < NCOPY * NG * 6; j += blockDim.x)
        ((float*)sacc)[j] = 0.f;
    __syncthreads();
    int w = (threadIdx.x >> 5) & (NCOPY - 1);
    int stride = gridDim.x * blockDim.x;
    const float4 z4 = make_float4(0.f, 0.f, 0.f, 0.f);
    for (int i = blockIdx.x * blockDim.x + threadIdx.x; i < NN; i += stride) {
        float di = d_dinv[i];
        float4 m = d_m[i];
        float4 z = d_a1[i];
        float n = d_n[i];
        int g = batch[i];
        // reset accumulators (still in cache)
        d_m[i] = z4;
        d_a1[i] = z4;
        d_n[i] = 0.f;
        d_degx[i] = 0.f;
        float* p = &sacc[w][g * 6];
        atomicAdd(p + 0, di * (m.x + z.x));
        atomicAdd(p + 1, di * (m.y + z.y));
        atomicAdd(p + 2, di * (m.z + z.z));
        atomicAdd(p + 3, di * (m.w + z.w));
        atomicAdd(p + 4, di * (n + di));
        atomicAdd(p + 5, 1.0f);
    }
    __syncthreads();
    for (int j = threadIdx.x; j < NG * 6; j += blockDim.x) {
        float v = 0.f;
        #pragma unroll
        for (int k = 0; k < NCOPY; k++) v += sacc[k][j];
        int g = j / 6, c = j % 6;
        red1(&d_acc[g * 8 + c], v);
    }
}

// One block, 64 threads: W0/W1 apply, BN over graphs, MLP; resets d_acc
__global__ void k_final(const float* __restrict__ W0, const float* __restrict__ b0,
                        const float* __restrict__ W1, const float* __restrict__ b1,
                        const float* __restrict__ bn1g, const float* __restrict__ bn1b,
                        const float* __restrict__ l0W, const float* __restrict__ l0b,
                        const float* __restrict__ l1W, const float* __restrict__ l1b,
                        const float* __restrict__ oW, const float* __restrict__ ob,
                        float* __restrict__ out) {
    __shared__ float sg[64][65];
    __shared__ float sW[64 * 64];
    int t = threadIdx.x;  // graph id / feature id

    for (int j = t; j < 4096; j += 64) sW[j] = W1[j];

    float* acc = &d_acc[t * 8];
    float s4[4];
    #pragma unroll
    for (int c = 0; c < 4; c++) s4[c] = acc[c];
    float ss = acc[4];
    float ng = acc[5];
    #pragma unroll
    for (int c = 0; c < 8; c++) acc[c] = 0.f;   // reset for next replay

    // h = s4 @ W0 + ss * b0
    float h[64];
    #pragma unroll
    for (int j = 0; j < 64; j++)
        h[j] = ss * b0[j] + s4[0] * W0[j] + s4[1] * W0[64 + j]
             + s4[2] * W0[128 + j] + s4[3] * W0[192 + j];
    __syncthreads();

    // g = h @ W1 + ng*b1
    for (int j = 0; j < 64; j++) {
        float a = ng * b1[j];
        #pragma unroll
        for (int k = 0; k < 64; k++) a += h[k] * sW[k * 64 + j];
        sg[t][j] = a;
    }
    __syncthreads();

    // BN1 over graphs, feature f = t
    {
        float m = 0.f;
        for (int G = 0; G < 64; G++) m += sg[G][t];
        m *= (1.0f / 64.0f);
        float v = 0.f;
        for (int G = 0; G < 64; G++) { float d = sg[G][t] - m; v += d * d; }
        v *= (1.0f / 64.0f);
        float r = rsqrtf(v + EPS) * bn1g[t];
        float bb = bn1b[t];
        for (int G = 0; G < 64; G++) sg[G][t] = (sg[G][t] - m) * r + bb;
    }
    __syncthreads();

    // lin0
    float h2[64];
    #pragma unroll
    for (int k = 0; k < 64; k++) h2[k] = sg[t][k];
    __syncthreads();
    for (int j = t; j < 4096; j += 64) sW[j] = l0W[j];
    __syncthreads();
    for (int j = 0; j < 64; j++) {
        float a = l0b[j];
        #pragma unroll
        for (int k = 0; k < 64; k++) a += h2[k] * sW[k * 64 + j];
        sg[t][j] = a;
    }
    __syncthreads();

    // lin1 + out fused
    #pragma unroll
    for (int k = 0; k < 64; k++) h2[k] = sg[t][k];
    __syncthreads();
    for (int j = t; j < 4096; j += 64) sW[j] = l1W[j];
    __syncthreads();
    float o = ob[0];
    for (int j = 0; j < 64; j++) {
        float a = l1b[j];
        #pragma unroll
        for (int k = 0; k < 64; k++) a += h2[k] * sW[k * 64 + j];
        o += a * oW[j];
    }
    out[t] = o;
}

extern "C" void kernel_launch(void* const* d_in, const int* in_sizes, int n_in,
                              void* d_out, int out_size) {
    const float* x     = (const float*)d_in[0];
    const int*   ei    = (const int*)d_in[1];
    const int*   batch = (const int*)d_in[2];
    const float* bn0g = (const float*)d_in[3];
    const float* bn0b = (const float*)d_in[4];
    const float* W0   = (const float*)d_in[5];
    const float* b0   = (const float*)d_in[6];
    const float* W1   = (const float*)d_in[7];
    const float* b1   = (const float*)d_in[8];
    const float* bn1g = (const float*)d_in[9];
    const float* bn1b = (const float*)d_in[10];
    const float* l0W  = (const float*)d_in[11];
    const float* l0b  = (const float*)d_in[12];
    const float* l1W  = (const float*)d_in[13];
    const float* l1b  = (const float*)d_in[14];
    const float* oW   = (const float*)d_in[15];
    const float* ob   = (const float*)d_in[16];
    float* out = (float*)d_out;

    int ethreads = NE / 4;  // 800K
    k_pre  <<<(ethreads + 255) / 256, 256>>>(x, ei);
    k_node1<<<(NN + 255) / 256, 256>>>(x, bn0g, bn0b);
    k_edge1<<<(ethreads + 255) / 256, 256>>>(ei);
    k_node2<<<(NN + 255) / 256, 256>>>();
    k_edge2<<<(ethreads + 255) / 256, 256>>>(ei);
    k_node3<<<148, 256>>>(batch);
    k_final<<<1, 64>>>(W0, b0, W1, b1, bn1g, bn1b,
                       l0W, l0b, l1W, l1b, oW, ob, out);
}